// round 1
// baseline (speedup 1.0000x reference)
#include <cuda_runtime.h>
#include <math.h>

#define T_TOKENS 4096
#define D_DIM    768
#define F_DIM    3072
#define E_EXP    8
#define NSLOTS   (T_TOKENS * 2)

// ---- scratch (static device allocations; runtime alloc is forbidden) ----
__device__ int   g_cnt[E_EXP];
__device__ int   g_off[E_EXP];
__device__ int   g_fill[E_EXP];
__device__ int   g_tok_e[T_TOKENS * 2];
__device__ float g_tok_w[T_TOKENS * 2];
__device__ int   g_tok_slot[T_TOKENS * 2];
__device__ int   g_slot_token[NSLOTS];
__device__ float g_h[(size_t)NSLOTS * F_DIM];   // 96 MB: gelu(fc) per slot
__device__ float g_y[(size_t)NSLOTS * D_DIM];   // 24 MB: proj out per slot

// ---------------------------------------------------------------- zero
__global__ void k_zero() {
    int i = threadIdx.x;
    if (i < E_EXP) { g_cnt[i] = 0; g_fill[i] = 0; }
}

// ---------------------------------------------------------------- router
// one warp per token: 8 dot-products of length 768, top-2, softmax(2)
__global__ void k_router(const float* __restrict__ x, const float* __restrict__ rw) {
    __shared__ float s_rw[E_EXP * D_DIM];
    for (int i = threadIdx.x; i < E_EXP * D_DIM; i += blockDim.x) s_rw[i] = rw[i];
    __syncthreads();
    int warp = threadIdx.x >> 5, lane = threadIdx.x & 31;
    int t = blockIdx.x * 8 + warp;
    if (t >= T_TOKENS) return;

    float xr[24];
#pragma unroll
    for (int i = 0; i < 24; i++) xr[i] = x[(size_t)t * D_DIM + lane + 32 * i];

    float logit[E_EXP];
#pragma unroll
    for (int e = 0; e < E_EXP; e++) {
        float p = 0.f;
#pragma unroll
        for (int i = 0; i < 24; i++) p = fmaf(xr[i], s_rw[e * D_DIM + lane + 32 * i], p);
#pragma unroll
        for (int o = 16; o; o >>= 1) p += __shfl_xor_sync(0xffffffffu, p, o);
        logit[e] = p;
    }
    if (lane == 0) {
        // top-1 (first max -> lowest index on tie, matching jax top_k)
        int e0 = 0; float v0 = logit[0];
#pragma unroll
        for (int e = 1; e < E_EXP; e++) if (logit[e] > v0) { v0 = logit[e]; e0 = e; }
        int e1 = 0; float v1 = -3.0e38f;
#pragma unroll
        for (int e = 0; e < E_EXP; e++) {
            if (e == e0) continue;
            if (logit[e] > v1) { v1 = logit[e]; e1 = e; }
        }
        float ex = expf(v1 - v0);            // v0 >= v1, stable softmax of 2
        float inv = 1.f / (1.f + ex);
        g_tok_e[t * 2 + 0] = e0;  g_tok_e[t * 2 + 1] = e1;
        g_tok_w[t * 2 + 0] = inv; g_tok_w[t * 2 + 1] = ex * inv;
        atomicAdd(&g_cnt[e0], 1);
        atomicAdd(&g_cnt[e1], 1);
    }
}

// ---------------------------------------------------------------- scan
__global__ void k_scan() {
    if (threadIdx.x == 0) {
        int s = 0;
        for (int e = 0; e < E_EXP; e++) { g_off[e] = s; s += g_cnt[e]; }
    }
}

// ---------------------------------------------------------------- fill
__global__ void k_fill() {
    int t = blockIdx.x * blockDim.x + threadIdx.x;
    if (t >= T_TOKENS) return;
#pragma unroll
    for (int k = 0; k < 2; k++) {
        int e = g_tok_e[t * 2 + k];
        int pos = atomicAdd(&g_fill[e], 1);
        int slot = g_off[e] + pos;
        g_slot_token[slot] = t;
        g_tok_slot[t * 2 + k] = slot;
    }
}

// ---------------------------------------------------------------- grouped GEMM
// GATHER: A rows gathered from x via slot->token; else A rows = g_h slots.
// DOGELU: epilogue = gelu(acc + bias) -> g_h ; else acc + bias -> g_y.
template <bool GATHER, bool DOGELU>
__global__ __launch_bounds__(256)
void k_gemm(const float* __restrict__ X, const float* __restrict__ W,
            const float* __restrict__ bias, int K, int N)
{
    const int BM = 128, BN = 128, BK = 16;
    __shared__ float As[BK][BM + 4];
    __shared__ float Bs[BK][BN];

    int e   = blockIdx.z;
    int cnt = g_cnt[e], off = g_off[e];
    int m0  = blockIdx.x * BM;
    if (m0 >= cnt) return;
    int n0 = blockIdx.y * BN;

    const float* Wp = W + (size_t)e * K * N;
    const float* Abase = GATHER ? X : g_h;
    float*       C     = DOGELU ? g_h : g_y;

    int tid = threadIdx.x;
    // A-load mapping: 512 float4 loads (128 rows x 4 k-chunks), 2 per thread
    int am0 = tid >> 2, am1 = am0 + 64;
    int akq = (tid & 3) * 4;
    const float *arow0, *arow1;
    if (GATHER) {
        int t0 = (m0 + am0 < cnt) ? g_slot_token[off + m0 + am0] : 0;
        int t1 = (m0 + am1 < cnt) ? g_slot_token[off + m0 + am1] : 0;
        arow0 = Abase + (size_t)t0 * K;
        arow1 = Abase + (size_t)t1 * K;
    } else {
        int s0 = off + min(m0 + am0, cnt - 1);
        int s1 = off + min(m0 + am1, cnt - 1);
        arow0 = Abase + (size_t)s0 * K;
        arow1 = Abase + (size_t)s1 * K;
    }
    // B-load mapping: 512 float4 (16 rows x 32 chunks), 2 per thread
    int bk = tid >> 5, bn = (tid & 31) * 4;
    int tx = tid & 15, ty = tid >> 4;

    float acc[8][8];
#pragma unroll
    for (int i = 0; i < 8; i++)
#pragma unroll
        for (int j = 0; j < 8; j++) acc[i][j] = 0.f;

    for (int k0 = 0; k0 < K; k0 += BK) {
        float4 a0 = *(const float4*)(arow0 + k0 + akq);
        float4 a1 = *(const float4*)(arow1 + k0 + akq);
        float4 b0 = *(const float4*)(Wp + (size_t)(k0 + bk)     * N + n0 + bn);
        float4 b1 = *(const float4*)(Wp + (size_t)(k0 + bk + 8) * N + n0 + bn);
        As[akq + 0][am0] = a0.x; As[akq + 1][am0] = a0.y;
        As[akq + 2][am0] = a0.z; As[akq + 3][am0] = a0.w;
        As[akq + 0][am1] = a1.x; As[akq + 1][am1] = a1.y;
        As[akq + 2][am1] = a1.z; As[akq + 3][am1] = a1.w;
        *(float4*)&Bs[bk][bn]     = b0;
        *(float4*)&Bs[bk + 8][bn] = b1;
        __syncthreads();
#pragma unroll
        for (int kk = 0; kk < BK; kk++) {
            float a[8], b[8];
#pragma unroll
            for (int i = 0; i < 8; i++) a[i] = As[kk][ty * 8 + i];
#pragma unroll
            for (int j = 0; j < 8; j++) b[j] = Bs[kk][tx * 8 + j];
#pragma unroll
            for (int i = 0; i < 8; i++)
#pragma unroll
                for (int j = 0; j < 8; j++) acc[i][j] = fmaf(a[i], b[j], acc[i][j]);
        }
        __syncthreads();
    }

    const float* bp = bias + (size_t)e * N + n0;
#pragma unroll
    for (int i = 0; i < 8; i++) {
        int m = ty * 8 + i;
        if (m0 + m >= cnt) continue;
        size_t orow = (size_t)(off + m0 + m) * N + n0;
#pragma unroll
        for (int j = 0; j < 8; j++) {
            int n = tx * 8 + j;
            float v = acc[i][j] + bp[n];
            if (DOGELU) v = 0.5f * v * (1.f + erff(v * 0.70710678118654752f));
            C[orow + n] = v;
        }
    }
}

// ---------------------------------------------------------------- combine
// out[t] = w0 * y[slot0] + w1 * y[slot1]   (atomic-free, deterministic)
__global__ void k_combine(float* __restrict__ out) {
    int idx = blockIdx.x * blockDim.x + threadIdx.x;
    const int NV = T_TOKENS * D_DIM / 4;
    if (idx >= NV) return;
    int t = idx / (D_DIM / 4);
    int c = idx % (D_DIM / 4);
    int   s0 = g_tok_slot[t * 2 + 0], s1 = g_tok_slot[t * 2 + 1];
    float w0 = g_tok_w[t * 2 + 0],    w1 = g_tok_w[t * 2 + 1];
    float4 y0 = *((const float4*)(g_y + (size_t)s0 * D_DIM) + c);
    float4 y1 = *((const float4*)(g_y + (size_t)s1 * D_DIM) + c);
    float4 r;
    r.x = w0 * y0.x + w1 * y1.x;
    r.y = w0 * y0.y + w1 * y1.y;
    r.z = w0 * y0.z + w1 * y1.z;
    r.w = w0 * y0.w + w1 * y1.w;
    *((float4*)out + idx) = r;
}

// ---------------------------------------------------------------- launch
extern "C" void kernel_launch(void* const* d_in, const int* in_sizes, int n_in,
                              void* d_out, int out_size)
{
    const float* x      = (const float*)d_in[0];
    const float* rw     = (const float*)d_in[1];
    const float* w_fc   = (const float*)d_in[2];
    const float* b_fc   = (const float*)d_in[3];
    const float* w_proj = (const float*)d_in[4];
    const float* b_proj = (const float*)d_in[5];
    float* out = (float*)d_out;

    k_zero<<<1, 32>>>();
    k_router<<<T_TOKENS / 8, 256>>>(x, rw);
    k_scan<<<1, 32>>>();
    k_fill<<<(T_TOKENS + 255) / 256, 256>>>();

    dim3 gfc(NSLOTS / 128, F_DIM / 128, E_EXP);   // (64, 24, 8)
    k_gemm<true, true><<<gfc, 256>>>(x, w_fc, b_fc, D_DIM, F_DIM);

    dim3 gpj(NSLOTS / 128, D_DIM / 128, E_EXP);   // (64, 6, 8)
    k_gemm<false, false><<<gpj, 256>>>(nullptr, w_proj, b_proj, F_DIM, D_DIM);

    k_combine<<<(T_TOKENS * D_DIM / 4 + 255) / 256, 256>>>(out);
}

// round 3
// speedup vs baseline: 2.6022x; 2.6022x over previous
#include <cuda_runtime.h>
#include <cuda_bf16.h>
#include <math.h>
#include <stdint.h>

#define T_TOKENS 4096
#define D_DIM    768
#define F_DIM    3072
#define E_EXP    8
#define NSLOTS   (T_TOKENS * 2)

// ------------------------------------------------------------------ scratch
__device__ int   g_cnt[E_EXP];
__device__ int   g_off[E_EXP];
__device__ int   g_fill[E_EXP];
__device__ int   g_tok_e[T_TOKENS * 2];
__device__ float g_tok_w[T_TOKENS * 2];
__device__ int   g_slot_token[NSLOTS];
__device__ float g_slot_w[NSLOTS];

__device__ __nv_bfloat16 g_ahi[(size_t)NSLOTS * D_DIM];
__device__ __nv_bfloat16 g_alo[(size_t)NSLOTS * D_DIM];
__device__ __nv_bfloat16 g_hhi[(size_t)NSLOTS * F_DIM];
__device__ __nv_bfloat16 g_hlo[(size_t)NSLOTS * F_DIM];
// transposed K-major weights: wfcT [E][F][D], wpjT [E][D][F]
__device__ __nv_bfloat16 g_wfchi[(size_t)E_EXP * F_DIM * D_DIM];
__device__ __nv_bfloat16 g_wfclo[(size_t)E_EXP * F_DIM * D_DIM];
__device__ __nv_bfloat16 g_wpjhi[(size_t)E_EXP * D_DIM * F_DIM];
__device__ __nv_bfloat16 g_wpjlo[(size_t)E_EXP * D_DIM * F_DIM];

// ------------------------------------------------------------------ helpers
__device__ __forceinline__ uint32_t smem_u32(const void* p) {
    uint32_t a;
    asm("{ .reg .u64 t; cvta.to.shared.u64 t, %1; cvt.u32.u64 %0, t; }" : "=r"(a) : "l"(p));
    return a;
}
__device__ __forceinline__ void cp16(uint32_t s, const void* g) {
    asm volatile("cp.async.cg.shared.global [%0], [%1], 16;" :: "r"(s), "l"(g));
}
#define CP_COMMIT() asm volatile("cp.async.commit_group;" ::: "memory")

__device__ __forceinline__ void ldsm4(uint32_t r[4], uint32_t addr) {
    asm volatile("ldmatrix.sync.aligned.m8n8.x4.shared.b16 {%0,%1,%2,%3}, [%4];"
                 : "=r"(r[0]), "=r"(r[1]), "=r"(r[2]), "=r"(r[3]) : "r"(addr));
}
__device__ __forceinline__ void mma16816(float c[4], const uint32_t a[4],
                                         uint32_t b0, uint32_t b1) {
    asm volatile("mma.sync.aligned.m16n8k16.row.col.f32.bf16.bf16.f32 "
                 "{%0,%1,%2,%3}, {%4,%5,%6,%7}, {%8,%9}, {%0,%1,%2,%3};"
                 : "+f"(c[0]), "+f"(c[1]), "+f"(c[2]), "+f"(c[3])
                 : "r"(a[0]), "r"(a[1]), "r"(a[2]), "r"(a[3]), "r"(b0), "r"(b1));
}

// ------------------------------------------------------------------ router path
__global__ void k_zero() {
    int i = threadIdx.x;
    if (i < E_EXP) { g_cnt[i] = 0; g_fill[i] = 0; }
}

__global__ void k_router(const float* __restrict__ x, const float* __restrict__ rw) {
    __shared__ float s_rw[E_EXP * D_DIM];
    for (int i = threadIdx.x; i < E_EXP * D_DIM; i += blockDim.x) s_rw[i] = rw[i];
    __syncthreads();
    int warp = threadIdx.x >> 5, lane = threadIdx.x & 31;
    int t = blockIdx.x * 8 + warp;
    if (t >= T_TOKENS) return;
    float xr[24];
#pragma unroll
    for (int i = 0; i < 24; i++) xr[i] = x[(size_t)t * D_DIM + lane + 32 * i];
    float logit[E_EXP];
#pragma unroll
    for (int e = 0; e < E_EXP; e++) {
        float p = 0.f;
#pragma unroll
        for (int i = 0; i < 24; i++) p = fmaf(xr[i], s_rw[e * D_DIM + lane + 32 * i], p);
#pragma unroll
        for (int o = 16; o; o >>= 1) p += __shfl_xor_sync(0xffffffffu, p, o);
        logit[e] = p;
    }
    if (lane == 0) {
        int e0 = 0; float v0 = logit[0];
#pragma unroll
        for (int e = 1; e < E_EXP; e++) if (logit[e] > v0) { v0 = logit[e]; e0 = e; }
        int e1 = 0; float v1 = -3.0e38f;
#pragma unroll
        for (int e = 0; e < E_EXP; e++) {
            if (e == e0) continue;
            if (logit[e] > v1) { v1 = logit[e]; e1 = e; }
        }
        float ex = expf(v1 - v0);
        float inv = 1.f / (1.f + ex);
        g_tok_e[t * 2 + 0] = e0;  g_tok_e[t * 2 + 1] = e1;
        g_tok_w[t * 2 + 0] = inv; g_tok_w[t * 2 + 1] = ex * inv;
        atomicAdd(&g_cnt[e0], 1);
        atomicAdd(&g_cnt[e1], 1);
    }
}

__global__ void k_scan() {
    if (threadIdx.x == 0) {
        int s = 0;
        for (int e = 0; e < E_EXP; e++) { g_off[e] = s; s += g_cnt[e]; }
    }
}

__global__ void k_fill() {
    int t = blockIdx.x * blockDim.x + threadIdx.x;
    if (t >= T_TOKENS) return;
#pragma unroll
    for (int k = 0; k < 2; k++) {
        int e = g_tok_e[t * 2 + k];
        int pos = atomicAdd(&g_fill[e], 1);
        int slot = g_off[e] + pos;
        g_slot_token[slot] = t;
        g_slot_w[slot] = g_tok_w[t * 2 + k];
    }
}

// gather + split x into slot-ordered bf16 hi/lo
__global__ void k_convx(const float* __restrict__ x) {
    int slot = blockIdx.x;
    int t = g_slot_token[slot];
    const float* xr = x + (size_t)t * D_DIM;
    size_t base = (size_t)slot * D_DIM;
    for (int i = threadIdx.x; i < D_DIM; i += blockDim.x) {
        float v = xr[i];
        __nv_bfloat16 h = __float2bfloat16(v);
        g_ahi[base + i] = h;
        g_alo[base + i] = __float2bfloat16(v - __bfloat162float(h));
    }
}

// transpose + split weights: src [E][K][N] fp32 -> dst [E][N][K] bf16 hi/lo
__global__ void k_convw(const float* __restrict__ src, int K, int N, int which) {
    __shared__ float tile[32][33];
    __nv_bfloat16* dhi = which ? g_wpjhi : g_wfchi;
    __nv_bfloat16* dlo = which ? g_wpjlo : g_wfclo;
    int e = blockIdx.z;
    int n0 = blockIdx.x * 32, k0 = blockIdx.y * 32;
    const float* s = src + (size_t)e * K * N;
#pragma unroll
    for (int dy = 0; dy < 32; dy += 8)
        tile[threadIdx.y + dy][threadIdx.x] =
            s[(size_t)(k0 + threadIdx.y + dy) * N + n0 + threadIdx.x];
    __syncthreads();
    size_t db = (size_t)e * N * K;
#pragma unroll
    for (int dy = 0; dy < 32; dy += 8) {
        int n = n0 + threadIdx.y + dy, k = k0 + threadIdx.x;
        float v = tile[threadIdx.x][threadIdx.y + dy];
        __nv_bfloat16 h = __float2bfloat16(v);
        dhi[db + (size_t)n * K + k] = h;
        dlo[db + (size_t)n * K + k] = __float2bfloat16(v - __bfloat162float(h));
    }
}

// ------------------------------------------------------------------ mma.sync grouped GEMM
// CTA 128x128, BK=64, 8 warps (warp tile 64x32), 2-stage cp.async pipe.
// 3-pass bf16 split (Ahi*Bhi + Ahi*Blo + Alo*Bhi) into fp32 accumulators.
#define OFF_AHI 0
#define OFF_ALO 16384
#define OFF_BHI 32768
#define OFF_BLO 49152
#define STAGE_BYTES 65536
#define GEMM_SMEM (2 * STAGE_BYTES + 1024)

// smem addr of (row, byte) inside a 128-row x 128B tile with SW128 xor swizzle
__device__ __forceinline__ uint32_t sw_addr(uint32_t tbase, int row, int byte) {
    uint32_t b = (uint32_t)(row * 128 + byte);
    return tbase + (b ^ ((b >> 3) & 0x70));
}

template <bool IS_FC>
__global__ __launch_bounds__(256, 1)
void k_mma_gemm(const float* __restrict__ bias, float* __restrict__ out)
{
    constexpr int Kdim = IS_FC ? D_DIM : F_DIM;
    constexpr int Ndim = IS_FC ? F_DIM : D_DIM;
    constexpr int NC = Kdim / 64;

    const int e   = blockIdx.z;
    const int cnt = g_cnt[e], off = g_off[e];
    const int m0  = blockIdx.x * 128;
    if (m0 >= cnt) return;
    const int n0 = blockIdx.y * 128;

    const __nv_bfloat16* Ahi = IS_FC ? g_ahi : g_hhi;
    const __nv_bfloat16* Alo = IS_FC ? g_alo : g_hlo;
    const __nv_bfloat16* Bhi = (IS_FC ? g_wfchi : g_wpjhi) + (size_t)e * Ndim * Kdim;
    const __nv_bfloat16* Blo = (IS_FC ? g_wfclo : g_wpjlo) + (size_t)e * Ndim * Kdim;

    extern __shared__ char smem_raw[];
    const uint32_t sbase = (smem_u32(smem_raw) + 1023) & ~1023u;

    const int tid = threadIdx.x;
    const int wid = tid >> 5, lid = tid & 31;
    const int wm = (wid >> 2) * 64;     // warp M offset (2 rows of warps)
    const int wn = (wid & 3) * 32;      // warp N offset (4 cols of warps)

    // ---- global load mappings (per thread: 4 A rows, 4 B rows, 16B chunk) ----
    const int c16 = tid & 7;
    size_t aOff[4], bOff[4];
    uint32_t sSw[4];
#pragma unroll
    for (int j = 0; j < 4; j++) {
        int row = (tid >> 3) + j * 32;                 // 0..127
        int gr  = off + min(m0 + row, cnt - 1);
        aOff[j] = (size_t)gr * (Kdim * 2) + c16 * 16;
        bOff[j] = (size_t)(n0 + row) * (Kdim * 2) + c16 * 16;
        uint32_t b = (uint32_t)(row * 128 + c16 * 16);
        sSw[j] = b ^ ((b >> 3) & 0x70);
    }
    const char* pAhi = (const char*)Ahi;
    const char* pAlo = (const char*)Alo;
    const char* pBhi = (const char*)Bhi;
    const char* pBlo = (const char*)Blo;

    auto load_chunk = [&](int chunk, int st) {
        uint32_t sb = sbase + st * STAGE_BYTES;
        size_t ko = (size_t)chunk * 128;               // 64 cols * 2B
#pragma unroll
        for (int j = 0; j < 4; j++) {
            cp16(sb + OFF_AHI + sSw[j], pAhi + aOff[j] + ko);
            cp16(sb + OFF_ALO + sSw[j], pAlo + aOff[j] + ko);
            cp16(sb + OFF_BHI + sSw[j], pBhi + bOff[j] + ko);
            cp16(sb + OFF_BLO + sSw[j], pBlo + bOff[j] + ko);
        }
        CP_COMMIT();
    };

    float acc[4][4][4];
#pragma unroll
    for (int i = 0; i < 4; i++)
#pragma unroll
        for (int j = 0; j < 4; j++)
#pragma unroll
            for (int c = 0; c < 4; c++) acc[i][j][c] = 0.f;

    load_chunk(0, 0);
    if (NC > 1) load_chunk(1, 1);

    // ldmatrix lane addressing components
    const int aRow = lid & 15;                  // A: row within 16-row group
    const int aHi16 = ((lid >> 4) & 1) * 16;    // A: +16B for k 8..15
    const int bRowSel = ((lid >> 4) & 1) * 8 + (lid & 7);  // B: row within 16-n group
    const int bHi16 = ((lid >> 3) & 1) * 16;

    for (int k = 0; k < NC; k++) {
        const int st = k & 1;
        if (k < NC - 1) asm volatile("cp.async.wait_group 1;" ::: "memory");
        else            asm volatile("cp.async.wait_group 0;" ::: "memory");
        __syncthreads();

        const uint32_t sb  = sbase + st * STAGE_BYTES;
        const uint32_t tAh = sb + OFF_AHI, tAl = sb + OFF_ALO;
        const uint32_t tBh = sb + OFF_BHI, tBl = sb + OFF_BLO;

#pragma unroll
        for (int q = 0; q < 4; q++) {              // 4 k16 steps per 64-chunk
            uint32_t ah[4][4], al[4][4], bh[2][4], bl[2][4];
#pragma unroll
            for (int mi = 0; mi < 4; mi++) {
                uint32_t adr = sw_addr(tAh, wm + mi * 16 + aRow, q * 32 + aHi16);
                ldsm4(ah[mi], adr);
                ldsm4(al[mi], adr + (OFF_ALO - OFF_AHI));
            }
#pragma unroll
            for (int nj2 = 0; nj2 < 2; nj2++) {
                uint32_t adr = sw_addr(tBh, wn + nj2 * 16 + bRowSel, q * 32 + bHi16);
                ldsm4(bh[nj2], adr);
                ldsm4(bl[nj2], adr + (OFF_BLO - OFF_BHI));
            }
#pragma unroll
            for (int mi = 0; mi < 4; mi++)
#pragma unroll
                for (int nj = 0; nj < 4; nj++) {
                    uint32_t b0 = bh[nj >> 1][(nj & 1) * 2];
                    uint32_t b1 = bh[nj >> 1][(nj & 1) * 2 + 1];
                    uint32_t l0 = bl[nj >> 1][(nj & 1) * 2];
                    uint32_t l1 = bl[nj >> 1][(nj & 1) * 2 + 1];
                    mma16816(acc[mi][nj], ah[mi], b0, b1);
                    mma16816(acc[mi][nj], ah[mi], l0, l1);
                    mma16816(acc[mi][nj], al[mi], b0, b1);
                }
        }
        __syncthreads();
        if (k + 2 < NC) load_chunk(k + 2, st);
    }

    // ---- epilogue ----
    const float* bp = bias + (size_t)e * Ndim + n0;
    const int rbase = wm + (lid >> 2);
    const int cquad = (lid & 3) * 2;

#pragma unroll
    for (int mi = 0; mi < 4; mi++) {
#pragma unroll
        for (int half = 0; half < 2; half++) {
            const int row = rbase + mi * 16 + half * 8;
            const int m = m0 + row;
            if (m >= cnt) continue;
            const int slot = off + m;
            int tok = 0; float wgt = 0.f;
            if (!IS_FC) { tok = g_slot_token[slot]; wgt = g_slot_w[slot]; }
#pragma unroll
            for (int nj = 0; nj < 4; nj++) {
                const int col = wn + nj * 8 + cquad;
                float v0 = acc[mi][nj][half * 2 + 0] + bp[col];
                float v1 = acc[mi][nj][half * 2 + 1] + bp[col + 1];
                if (IS_FC) {
                    float g0 = 0.5f * v0 * (1.f + erff(v0 * 0.70710678118654752f));
                    float g1 = 0.5f * v1 * (1.f + erff(v1 * 0.70710678118654752f));
                    __nv_bfloat16 h0 = __float2bfloat16(g0);
                    __nv_bfloat16 h1 = __float2bfloat16(g1);
                    __nv_bfloat16 q0 = __float2bfloat16(g0 - __bfloat162float(h0));
                    __nv_bfloat16 q1 = __float2bfloat16(g1 - __bfloat162float(h1));
                    size_t idx = (size_t)slot * Ndim + n0 + col;
                    *(uint32_t*)(g_hhi + idx) =
                        (uint32_t)__bfloat16_as_ushort(h0) |
                        ((uint32_t)__bfloat16_as_ushort(h1) << 16);
                    *(uint32_t*)(g_hlo + idx) =
                        (uint32_t)__bfloat16_as_ushort(q0) |
                        ((uint32_t)__bfloat16_as_ushort(q1) << 16);
                } else {
                    float* op = out + (size_t)tok * D_DIM + n0 + col;
                    atomicAdd(op + 0, v0 * wgt);
                    atomicAdd(op + 1, v1 * wgt);
                }
            }
        }
    }
}

// ------------------------------------------------------------------ launch
extern "C" void kernel_launch(void* const* d_in, const int* in_sizes, int n_in,
                              void* d_out, int out_size)
{
    const float* x      = (const float*)d_in[0];
    const float* rw     = (const float*)d_in[1];
    const float* w_fc   = (const float*)d_in[2];
    const float* b_fc   = (const float*)d_in[3];
    const float* w_proj = (const float*)d_in[4];
    const float* b_proj = (const float*)d_in[5];
    float* out = (float*)d_out;

    cudaFuncSetAttribute(k_mma_gemm<true>,  cudaFuncAttributeMaxDynamicSharedMemorySize, GEMM_SMEM);
    cudaFuncSetAttribute(k_mma_gemm<false>, cudaFuncAttributeMaxDynamicSharedMemorySize, GEMM_SMEM);

    cudaMemsetAsync(out, 0, (size_t)out_size * sizeof(float));

    k_zero<<<1, 32>>>();
    k_router<<<T_TOKENS / 8, 256>>>(x, rw);
    k_scan<<<1, 32>>>();
    k_fill<<<(T_TOKENS + 255) / 256, 256>>>();
    k_convx<<<NSLOTS, 256>>>(x);

    dim3 bw(32, 8);
    k_convw<<<dim3(F_DIM / 32, D_DIM / 32, E_EXP), bw>>>(w_fc,   D_DIM, F_DIM, 0);
    k_convw<<<dim3(D_DIM / 32, F_DIM / 32, E_EXP), bw>>>(w_proj, F_DIM, D_DIM, 1);

    k_mma_gemm<true ><<<dim3(NSLOTS / 128, F_DIM / 128, E_EXP), 256, GEMM_SMEM>>>(b_fc, nullptr);
    k_mma_gemm<false><<<dim3(NSLOTS / 128, D_DIM / 128, E_EXP), 256, GEMM_SMEM>>>(b_proj, out);
}

// round 4
// speedup vs baseline: 2.6746x; 1.0278x over previous
#include <cuda_runtime.h>
#include <cuda_bf16.h>
#include <math.h>
#include <stdint.h>

#define T_TOKENS 4096
#define D_DIM    768
#define F_DIM    3072
#define E_EXP    8
#define EXP_CAP  4096                    // max tokens per expert (top-2 distinct)
#define NSLOTS   (E_EXP * EXP_CAP)       // fixed-stride slot space

// ------------------------------------------------------------------ scratch
__device__ int   g_fill[E_EXP];          // per-expert counts (zeroed by memset)
__device__ int   g_slot_token[NSLOTS];
__device__ float g_slot_w[NSLOTS];

__device__ __nv_bfloat16 g_ahi[(size_t)NSLOTS * D_DIM];
__device__ __nv_bfloat16 g_alo[(size_t)NSLOTS * D_DIM];
__device__ __nv_bfloat16 g_hhi[(size_t)NSLOTS * F_DIM];
__device__ __nv_bfloat16 g_hlo[(size_t)NSLOTS * F_DIM];
// transposed K-major weights: wfcT [E][F][D], wpjT [E][D][F]
__device__ __nv_bfloat16 g_wfchi[(size_t)E_EXP * F_DIM * D_DIM];
__device__ __nv_bfloat16 g_wfclo[(size_t)E_EXP * F_DIM * D_DIM];
__device__ __nv_bfloat16 g_wpjhi[(size_t)E_EXP * D_DIM * F_DIM];
__device__ __nv_bfloat16 g_wpjlo[(size_t)E_EXP * D_DIM * F_DIM];

// ------------------------------------------------------------------ helpers
__device__ __forceinline__ uint32_t smem_u32(const void* p) {
    uint32_t a;
    asm("{ .reg .u64 t; cvta.to.shared.u64 t, %1; cvt.u32.u64 %0, t; }" : "=r"(a) : "l"(p));
    return a;
}
__device__ __forceinline__ void cp16(uint32_t s, const void* g) {
    asm volatile("cp.async.cg.shared.global [%0], [%1], 16;" :: "r"(s), "l"(g));
}
#define CP_COMMIT() asm volatile("cp.async.commit_group;" ::: "memory")

__device__ __forceinline__ void ldsm4(uint32_t r[4], uint32_t addr) {
    asm volatile("ldmatrix.sync.aligned.m8n8.x4.shared.b16 {%0,%1,%2,%3}, [%4];"
                 : "=r"(r[0]), "=r"(r[1]), "=r"(r[2]), "=r"(r[3]) : "r"(addr));
}
__device__ __forceinline__ void mma16816(float c[4], const uint32_t a[4],
                                         uint32_t b0, uint32_t b1) {
    asm volatile("mma.sync.aligned.m16n8k16.row.col.f32.bf16.bf16.f32 "
                 "{%0,%1,%2,%3}, {%4,%5,%6,%7}, {%8,%9}, {%0,%1,%2,%3};"
                 : "+f"(c[0]), "+f"(c[1]), "+f"(c[2]), "+f"(c[3])
                 : "r"(a[0]), "r"(a[1]), "r"(a[2]), "r"(a[3]), "r"(b0), "r"(b1));
}

// ------------------------------------------------------------------ weight convert
// transpose + split weights: src [E][K][N] fp32 -> dst [E][N][K] bf16 hi/lo
__global__ void k_convw(const float* __restrict__ src, int K, int N, int which) {
    __shared__ float tile[32][33];
    __nv_bfloat16* dhi = which ? g_wpjhi : g_wfchi;
    __nv_bfloat16* dlo = which ? g_wpjlo : g_wfclo;
    int e = blockIdx.z;
    int n0 = blockIdx.x * 32, k0 = blockIdx.y * 32;
    const float* s = src + (size_t)e * K * N;
#pragma unroll
    for (int dy = 0; dy < 32; dy += 8)
        tile[threadIdx.y + dy][threadIdx.x] =
            s[(size_t)(k0 + threadIdx.y + dy) * N + n0 + threadIdx.x];
    __syncthreads();
    size_t db = (size_t)e * N * K;
#pragma unroll
    for (int dy = 0; dy < 32; dy += 8) {
        int n = n0 + threadIdx.y + dy, k = k0 + threadIdx.x;
        float v = tile[threadIdx.x][threadIdx.y + dy];
        __nv_bfloat16 h = __float2bfloat16(v);
        dhi[db + (size_t)n * K + k] = h;
        dlo[db + (size_t)n * K + k] = __float2bfloat16(v - __bfloat162float(h));
    }
}

// ------------------------------------------------------------------ fused router + slot fill + x split
// one warp per token: logits, top-2, softmax(2), slot alloc, gather+split x.
__global__ void k_router(const float* __restrict__ x, const float* __restrict__ rw) {
    __shared__ float s_rw[E_EXP * D_DIM];
    for (int i = threadIdx.x; i < E_EXP * D_DIM; i += blockDim.x) s_rw[i] = rw[i];
    __syncthreads();
    int warp = threadIdx.x >> 5, lane = threadIdx.x & 31;
    int t = blockIdx.x * 8 + warp;
    if (t >= T_TOKENS) return;

    const float* xrow = x + (size_t)t * D_DIM;
    float xr[24];
#pragma unroll
    for (int i = 0; i < 24; i++) xr[i] = xrow[lane + 32 * i];

    float logit[E_EXP];
#pragma unroll
    for (int e = 0; e < E_EXP; e++) {
        float p = 0.f;
#pragma unroll
        for (int i = 0; i < 24; i++) p = fmaf(xr[i], s_rw[e * D_DIM + lane + 32 * i], p);
#pragma unroll
        for (int o = 16; o; o >>= 1) p += __shfl_xor_sync(0xffffffffu, p, o);
        logit[e] = p;
    }
    int slot0 = 0, slot1 = 0;
    if (lane == 0) {
        int e0 = 0; float v0 = logit[0];
#pragma unroll
        for (int e = 1; e < E_EXP; e++) if (logit[e] > v0) { v0 = logit[e]; e0 = e; }
        int e1 = 0; float v1 = -3.0e38f;
#pragma unroll
        for (int e = 0; e < E_EXP; e++) {
            if (e == e0) continue;
            if (logit[e] > v1) { v1 = logit[e]; e1 = e; }
        }
        float ex = expf(v1 - v0);                  // v0 >= v1, stable 2-way softmax
        float inv = 1.f / (1.f + ex);
        slot0 = e0 * EXP_CAP + atomicAdd(&g_fill[e0], 1);
        slot1 = e1 * EXP_CAP + atomicAdd(&g_fill[e1], 1);
        g_slot_token[slot0] = t;  g_slot_w[slot0] = inv;
        g_slot_token[slot1] = t;  g_slot_w[slot1] = ex * inv;
    }
    slot0 = __shfl_sync(0xffffffffu, slot0, 0);
    slot1 = __shfl_sync(0xffffffffu, slot1, 0);

    // split x into bf16 hi/lo at both slot rows
#pragma unroll
    for (int i = 0; i < 24; i++) {
        float v = xr[i];
        __nv_bfloat16 h = __float2bfloat16(v);
        __nv_bfloat16 l = __float2bfloat16(v - __bfloat162float(h));
        int c = lane + 32 * i;
        g_ahi[(size_t)slot0 * D_DIM + c] = h;
        g_alo[(size_t)slot0 * D_DIM + c] = l;
        g_ahi[(size_t)slot1 * D_DIM + c] = h;
        g_alo[(size_t)slot1 * D_DIM + c] = l;
    }
}

// ------------------------------------------------------------------ mma.sync grouped GEMM
// CTA 128x128, BK=64, 8 warps (warp tile 64x32), 3-stage cp.async pipe.
// 3-pass bf16 split (Ahi*Bhi + Ahi*Blo + Alo*Bhi) into fp32 accumulators.
#define OFF_AHI 0
#define OFF_ALO 16384
#define OFF_BHI 32768
#define OFF_BLO 49152
#define STAGE_BYTES 65536
#define N_STAGES 3
#define GEMM_SMEM (N_STAGES * STAGE_BYTES + 1024)

// smem addr of (row, byte) inside a 128-row x 128B tile with SW128 xor swizzle
__device__ __forceinline__ uint32_t sw_addr(uint32_t tbase, int row, int byte) {
    uint32_t b = (uint32_t)(row * 128 + byte);
    return tbase + (b ^ ((b >> 3) & 0x70));
}

template <bool IS_FC>
__global__ __launch_bounds__(256, 1)
void k_mma_gemm(const float* __restrict__ bias, float* __restrict__ out)
{
    constexpr int Kdim = IS_FC ? D_DIM : F_DIM;
    constexpr int Ndim = IS_FC ? F_DIM : D_DIM;
    constexpr int NC = Kdim / 64;

    const int e   = blockIdx.z;
    const int cnt = g_fill[e];
    const int off = e * EXP_CAP;
    const int m0  = blockIdx.x * 128;
    if (m0 >= cnt) return;
    const int n0 = blockIdx.y * 128;

    const __nv_bfloat16* Ahi = IS_FC ? g_ahi : g_hhi;
    const __nv_bfloat16* Alo = IS_FC ? g_alo : g_hlo;
    const __nv_bfloat16* Bhi = (IS_FC ? g_wfchi : g_wpjhi) + (size_t)e * Ndim * Kdim;
    const __nv_bfloat16* Blo = (IS_FC ? g_wfclo : g_wpjlo) + (size_t)e * Ndim * Kdim;

    extern __shared__ char smem_raw[];
    const uint32_t sbase = (smem_u32(smem_raw) + 1023) & ~1023u;

    const int tid = threadIdx.x;
    const int wid = tid >> 5, lid = tid & 31;
    const int wm = (wid >> 2) * 64;     // warp M offset
    const int wn = (wid & 3) * 32;      // warp N offset

    // ---- global load mappings (per thread: 4 A rows, 4 B rows, 16B chunk) ----
    const int c16 = tid & 7;
    size_t aOff[4], bOff[4];
    uint32_t sSw[4];
#pragma unroll
    for (int j = 0; j < 4; j++) {
        int row = (tid >> 3) + j * 32;                 // 0..127
        int gr  = off + min(m0 + row, cnt - 1);
        aOff[j] = (size_t)gr * (Kdim * 2) + c16 * 16;
        bOff[j] = (size_t)(n0 + row) * (Kdim * 2) + c16 * 16;
        uint32_t b = (uint32_t)(row * 128 + c16 * 16);
        sSw[j] = b ^ ((b >> 3) & 0x70);
    }
    const char* pAhi = (const char*)Ahi;
    const char* pAlo = (const char*)Alo;
    const char* pBhi = (const char*)Bhi;
    const char* pBlo = (const char*)Blo;

    auto load_chunk = [&](int chunk, int st) {
        uint32_t sb = sbase + st * STAGE_BYTES;
        size_t ko = (size_t)chunk * 128;               // 64 cols * 2B
#pragma unroll
        for (int j = 0; j < 4; j++) {
            cp16(sb + OFF_AHI + sSw[j], pAhi + aOff[j] + ko);
            cp16(sb + OFF_ALO + sSw[j], pAlo + aOff[j] + ko);
            cp16(sb + OFF_BHI + sSw[j], pBhi + bOff[j] + ko);
            cp16(sb + OFF_BLO + sSw[j], pBlo + bOff[j] + ko);
        }
        CP_COMMIT();
    };

    float acc[4][4][4];
#pragma unroll
    for (int i = 0; i < 4; i++)
#pragma unroll
        for (int j = 0; j < 4; j++)
#pragma unroll
            for (int c = 0; c < 4; c++) acc[i][j][c] = 0.f;

    // prologue: 2 chunks in flight
    load_chunk(0, 0);
    if (NC > 1) load_chunk(1, 1);

    // ldmatrix lane addressing components
    const int aRow = lid & 15;
    const int aHi16 = ((lid >> 4) & 1) * 16;
    const int bRowSel = ((lid >> 4) & 1) * 8 + (lid & 7);
    const int bHi16 = ((lid >> 3) & 1) * 16;

    for (int k = 0; k < NC; k++) {
        const int st = k % N_STAGES;
        if (k < NC - 1) asm volatile("cp.async.wait_group 1;" ::: "memory");
        else            asm volatile("cp.async.wait_group 0;" ::: "memory");
        __syncthreads();
        // issue the next load BEFORE compute; its target stage ((k+2)%3 == (k-1)%3)
        // was freed by the sync above (all threads finished chunk k-1).
        if (k + 2 < NC) load_chunk(k + 2, (k + 2) % N_STAGES);

        const uint32_t sb  = sbase + st * STAGE_BYTES;
        const uint32_t tAh = sb + OFF_AHI;
        const uint32_t tBh = sb + OFF_BHI;

#pragma unroll
        for (int q = 0; q < 4; q++) {              // 4 k16 steps per 64-chunk
            uint32_t ah[4][4], al[4][4], bh[2][4], bl[2][4];
#pragma unroll
            for (int mi = 0; mi < 4; mi++) {
                uint32_t adr = sw_addr(tAh, wm + mi * 16 + aRow, q * 32 + aHi16);
                ldsm4(ah[mi], adr);
                ldsm4(al[mi], adr + (OFF_ALO - OFF_AHI));
            }
#pragma unroll
            for (int nj2 = 0; nj2 < 2; nj2++) {
                uint32_t adr = sw_addr(tBh, wn + nj2 * 16 + bRowSel, q * 32 + bHi16);
                ldsm4(bh[nj2], adr);
                ldsm4(bl[nj2], adr + (OFF_BLO - OFF_BHI));
            }
#pragma unroll
            for (int mi = 0; mi < 4; mi++)
#pragma unroll
                for (int nj = 0; nj < 4; nj++) {
                    uint32_t b0 = bh[nj >> 1][(nj & 1) * 2];
                    uint32_t b1 = bh[nj >> 1][(nj & 1) * 2 + 1];
                    uint32_t l0 = bl[nj >> 1][(nj & 1) * 2];
                    uint32_t l1 = bl[nj >> 1][(nj & 1) * 2 + 1];
                    mma16816(acc[mi][nj], ah[mi], b0, b1);
                    mma16816(acc[mi][nj], ah[mi], l0, l1);
                    mma16816(acc[mi][nj], al[mi], b0, b1);
                }
        }
        __syncthreads();   // protect stage st: loads into it resume next iterations
    }

    // ---- epilogue ----
    const float* bp = bias + (size_t)e * Ndim + n0;
    const int rbase = wm + (lid >> 2);
    const int cquad = (lid & 3) * 2;

#pragma unroll
    for (int mi = 0; mi < 4; mi++) {
#pragma unroll
        for (int half = 0; half < 2; half++) {
            const int row = rbase + mi * 16 + half * 8;
            const int m = m0 + row;
            if (m >= cnt) continue;
            const int slot = off + m;
            int tok = 0; float wgt = 0.f;
            if (!IS_FC) { tok = g_slot_token[slot]; wgt = g_slot_w[slot]; }
#pragma unroll
            for (int nj = 0; nj < 4; nj++) {
                const int col = wn + nj * 8 + cquad;
                float v0 = acc[mi][nj][half * 2 + 0] + bp[col];
                float v1 = acc[mi][nj][half * 2 + 1] + bp[col + 1];
                if (IS_FC) {
                    float g0 = 0.5f * v0 * (1.f + erff(v0 * 0.70710678118654752f));
                    float g1 = 0.5f * v1 * (1.f + erff(v1 * 0.70710678118654752f));
                    __nv_bfloat16 h0 = __float2bfloat16(g0);
                    __nv_bfloat16 h1 = __float2bfloat16(g1);
                    __nv_bfloat16 q0 = __float2bfloat16(g0 - __bfloat162float(h0));
                    __nv_bfloat16 q1 = __float2bfloat16(g1 - __bfloat162float(h1));
                    size_t idx = (size_t)slot * Ndim + n0 + col;
                    *(uint32_t*)(g_hhi + idx) =
                        (uint32_t)__bfloat16_as_ushort(h0) |
                        ((uint32_t)__bfloat16_as_ushort(h1) << 16);
                    *(uint32_t*)(g_hlo + idx) =
                        (uint32_t)__bfloat16_as_ushort(q0) |
                        ((uint32_t)__bfloat16_as_ushort(q1) << 16);
                } else {
                    float* op = out + (size_t)tok * D_DIM + n0 + col;
                    atomicAdd(op + 0, v0 * wgt);
                    atomicAdd(op + 1, v1 * wgt);
                }
            }
        }
    }
}

// ------------------------------------------------------------------ launch
extern "C" void kernel_launch(void* const* d_in, const int* in_sizes, int n_in,
                              void* d_out, int out_size)
{
    const float* x      = (const float*)d_in[0];
    const float* rw     = (const float*)d_in[1];
    const float* w_fc   = (const float*)d_in[2];
    const float* b_fc   = (const float*)d_in[3];
    const float* w_proj = (const float*)d_in[4];
    const float* b_proj = (const float*)d_in[5];
    float* out = (float*)d_out;

    cudaFuncSetAttribute(k_mma_gemm<true>,  cudaFuncAttributeMaxDynamicSharedMemorySize, GEMM_SMEM);
    cudaFuncSetAttribute(k_mma_gemm<false>, cudaFuncAttributeMaxDynamicSharedMemorySize, GEMM_SMEM);

    cudaMemsetAsync(out, 0, (size_t)out_size * sizeof(float));
    void* pfill = nullptr;
    cudaGetSymbolAddress(&pfill, g_fill);
    cudaMemsetAsync(pfill, 0, E_EXP * sizeof(int));

    dim3 bw(32, 8);
    k_convw<<<dim3(F_DIM / 32, D_DIM / 32, E_EXP), bw>>>(w_fc,   D_DIM, F_DIM, 0);  // #1
    k_convw<<<dim3(D_DIM / 32, F_DIM / 32, E_EXP), bw>>>(w_proj, F_DIM, D_DIM, 1);  // #2

    k_router<<<T_TOKENS / 8, 256>>>(x, rw);                                          // #3

    k_mma_gemm<true ><<<dim3(EXP_CAP / 128, F_DIM / 128, E_EXP), 256, GEMM_SMEM>>>(b_fc, nullptr);  // #4 (profiled)
    k_mma_gemm<false><<<dim3(EXP_CAP / 128, D_DIM / 128, E_EXP), 256, GEMM_SMEM>>>(b_proj, out);    // #5
}

// round 5
// speedup vs baseline: 2.8275x; 1.0572x over previous
#include <cuda_runtime.h>
#include <cuda_bf16.h>
#include <math.h>
#include <stdint.h>

#define T_TOKENS 4096
#define D_DIM    768
#define F_DIM    3072
#define E_EXP    8
#define EXP_CAP  4096
#define NSLOTS   (E_EXP * EXP_CAP)

// ------------------------------------------------------------------ scratch
__device__ int   g_fill[E_EXP];          // zeroed by memset each call
__device__ int   g_slot_token[NSLOTS];
__device__ float g_slot_w[NSLOTS];

__device__ __nv_bfloat16 g_ahi[(size_t)NSLOTS * D_DIM];
__device__ __nv_bfloat16 g_alo[(size_t)NSLOTS * D_DIM];
__device__ __nv_bfloat16 g_hhi[(size_t)NSLOTS * F_DIM];
__device__ __nv_bfloat16 g_hlo[(size_t)NSLOTS * F_DIM];
// transposed K-major weights: wfcT [E][F][D], wpjT [E][D][F]
__device__ __nv_bfloat16 g_wfchi[(size_t)E_EXP * F_DIM * D_DIM];
__device__ __nv_bfloat16 g_wfclo[(size_t)E_EXP * F_DIM * D_DIM];
__device__ __nv_bfloat16 g_wpjhi[(size_t)E_EXP * D_DIM * F_DIM];
__device__ __nv_bfloat16 g_wpjlo[(size_t)E_EXP * D_DIM * F_DIM];

// ------------------------------------------------------------------ helpers
__device__ __forceinline__ uint32_t smem_u32(const void* p) {
    uint32_t a;
    asm("{ .reg .u64 t; cvta.to.shared.u64 t, %1; cvt.u32.u64 %0, t; }" : "=r"(a) : "l"(p));
    return a;
}
__device__ __forceinline__ void cp16(uint32_t s, const void* g) {
    asm volatile("cp.async.cg.shared.global [%0], [%1], 16;" :: "r"(s), "l"(g));
}
#define CP_COMMIT() asm volatile("cp.async.commit_group;" ::: "memory")

__device__ __forceinline__ void ldsm4(uint32_t r[4], uint32_t addr) {
    asm volatile("ldmatrix.sync.aligned.m8n8.x4.shared.b16 {%0,%1,%2,%3}, [%4];"
                 : "=r"(r[0]), "=r"(r[1]), "=r"(r[2]), "=r"(r[3]) : "r"(addr));
}
__device__ __forceinline__ void mma16816(float c[4], const uint32_t a[4],
                                         uint32_t b0, uint32_t b1) {
    asm volatile("mma.sync.aligned.m16n8k16.row.col.f32.bf16.bf16.f32 "
                 "{%0,%1,%2,%3}, {%4,%5,%6,%7}, {%8,%9}, {%0,%1,%2,%3};"
                 : "+f"(c[0]), "+f"(c[1]), "+f"(c[2]), "+f"(c[3])
                 : "r"(a[0]), "r"(a[1]), "r"(a[2]), "r"(a[3]), "r"(b0), "r"(b1));
}

// ------------------------------------------------------------------ weight convert
__global__ void k_convw(const float* __restrict__ src, int K, int N, int which) {
    __shared__ float tile[32][33];
    __nv_bfloat16* dhi = which ? g_wpjhi : g_wfchi;
    __nv_bfloat16* dlo = which ? g_wpjlo : g_wfclo;
    int e = blockIdx.z;
    int n0 = blockIdx.x * 32, k0 = blockIdx.y * 32;
    const float* s = src + (size_t)e * K * N;
#pragma unroll
    for (int dy = 0; dy < 32; dy += 8)
        tile[threadIdx.y + dy][threadIdx.x] =
            s[(size_t)(k0 + threadIdx.y + dy) * N + n0 + threadIdx.x];
    __syncthreads();
    size_t db = (size_t)e * N * K;
#pragma unroll
    for (int dy = 0; dy < 32; dy += 8) {
        int n = n0 + threadIdx.y + dy, k = k0 + threadIdx.x;
        float v = tile[threadIdx.x][threadIdx.y + dy];
        __nv_bfloat16 h = __float2bfloat16(v);
        dhi[db + (size_t)n * K + k] = h;
        dlo[db + (size_t)n * K + k] = __float2bfloat16(v - __bfloat162float(h));
    }
}

// ------------------------------------------------------------------ fused router + slot fill + x split
__global__ void k_router(const float* __restrict__ x, const float* __restrict__ rw) {
    __shared__ float s_rw[E_EXP * D_DIM];
    for (int i = threadIdx.x; i < E_EXP * D_DIM; i += blockDim.x) s_rw[i] = rw[i];
    __syncthreads();
    int warp = threadIdx.x >> 5, lane = threadIdx.x & 31;
    int t = blockIdx.x * 8 + warp;
    if (t >= T_TOKENS) return;

    const float* xrow = x + (size_t)t * D_DIM;
    float xr[24];
#pragma unroll
    for (int i = 0; i < 24; i++) xr[i] = xrow[lane + 32 * i];

    float logit[E_EXP];
#pragma unroll
    for (int e = 0; e < E_EXP; e++) {
        float p = 0.f;
#pragma unroll
        for (int i = 0; i < 24; i++) p = fmaf(xr[i], s_rw[e * D_DIM + lane + 32 * i], p);
#pragma unroll
        for (int o = 16; o; o >>= 1) p += __shfl_xor_sync(0xffffffffu, p, o);
        logit[e] = p;
    }
    int slot0 = 0, slot1 = 0;
    if (lane == 0) {
        int e0 = 0; float v0 = logit[0];
#pragma unroll
        for (int e = 1; e < E_EXP; e++) if (logit[e] > v0) { v0 = logit[e]; e0 = e; }
        int e1 = 0; float v1 = -3.0e38f;
#pragma unroll
        for (int e = 0; e < E_EXP; e++) {
            if (e == e0) continue;
            if (logit[e] > v1) { v1 = logit[e]; e1 = e; }
        }
        float ex = expf(v1 - v0);
        float inv = 1.f / (1.f + ex);
        slot0 = e0 * EXP_CAP + atomicAdd(&g_fill[e0], 1);
        slot1 = e1 * EXP_CAP + atomicAdd(&g_fill[e1], 1);
        g_slot_token[slot0] = t;  g_slot_w[slot0] = inv;
        g_slot_token[slot1] = t;  g_slot_w[slot1] = ex * inv;
    }
    slot0 = __shfl_sync(0xffffffffu, slot0, 0);
    slot1 = __shfl_sync(0xffffffffu, slot1, 0);

#pragma unroll
    for (int i = 0; i < 24; i++) {
        float v = xr[i];
        __nv_bfloat16 h = __float2bfloat16(v);
        __nv_bfloat16 l = __float2bfloat16(v - __bfloat162float(h));
        int c = lane + 32 * i;
        g_ahi[(size_t)slot0 * D_DIM + c] = h;
        g_alo[(size_t)slot0 * D_DIM + c] = l;
        g_ahi[(size_t)slot1 * D_DIM + c] = h;
        g_alo[(size_t)slot1 * D_DIM + c] = l;
    }
}

// ------------------------------------------------------------------ mma.sync grouped GEMM
// CTA 128x64 (128 threads, 4 warps, warp tile 64x32), BK=64, 2-stage cp.async pipe,
// 2 CTAs/SM for cross-CTA latency hiding. Register-fragment double buffering.
// 3-pass bf16 split (Ahi*Bhi + Ahi*Blo + Alo*Bhi) into fp32 accumulators.
#define OFF_AHI 0
#define OFF_ALO 16384
#define OFF_BHI 32768
#define OFF_BLO 40960
#define STAGE_BYTES 49152
#define N_STAGES 2
#define GEMM_SMEM (N_STAGES * STAGE_BYTES + 1024)

__device__ __forceinline__ uint32_t sw_addr(uint32_t tbase, int row, int byte) {
    uint32_t b = (uint32_t)(row * 128 + byte);
    return tbase + (b ^ ((b >> 3) & 0x70));
}

template <bool IS_FC>
__global__ __launch_bounds__(128, 2)
void k_mma_gemm(const float* __restrict__ bias, float* __restrict__ out)
{
    constexpr int Kdim = IS_FC ? D_DIM : F_DIM;
    constexpr int Ndim = IS_FC ? F_DIM : D_DIM;
    constexpr int NC = Kdim / 64;

    const int e   = blockIdx.z;
    const int cnt = g_fill[e];
    const int off = e * EXP_CAP;
    const int m0  = blockIdx.x * 128;
    if (m0 >= cnt) return;
    const int n0 = blockIdx.y * 64;

    const __nv_bfloat16* Ahi = IS_FC ? g_ahi : g_hhi;
    const __nv_bfloat16* Alo = IS_FC ? g_alo : g_hlo;
    const __nv_bfloat16* Bhi = (IS_FC ? g_wfchi : g_wpjhi) + (size_t)e * Ndim * Kdim;
    const __nv_bfloat16* Blo = (IS_FC ? g_wfclo : g_wpjlo) + (size_t)e * Ndim * Kdim;

    extern __shared__ char smem_raw[];
    const uint32_t sbase = (smem_u32(smem_raw) + 1023) & ~1023u;

    const int tid = threadIdx.x;
    const int wid = tid >> 5, lid = tid & 31;
    const int wm = (wid >> 1) * 64;     // warp M offset (2x2 warp grid)
    const int wn = (wid & 1) * 32;      // warp N offset

    // ---- global load mappings: 128 threads, 8 A rows + 4 B rows each ----
    const int c16 = tid & 7;
    size_t aOff[8], bOff[4];
    uint32_t aSw[8], bSw[4];
#pragma unroll
    for (int j = 0; j < 8; j++) {
        int row = (tid >> 3) + j * 16;                 // 0..127
        int gr  = off + min(m0 + row, cnt - 1);
        aOff[j] = (size_t)gr * (Kdim * 2) + c16 * 16;
        uint32_t b = (uint32_t)(row * 128 + c16 * 16);
        aSw[j] = b ^ ((b >> 3) & 0x70);
    }
#pragma unroll
    for (int j = 0; j < 4; j++) {
        int row = (tid >> 3) + j * 16;                 // 0..63
        bOff[j] = (size_t)(n0 + row) * (Kdim * 2) + c16 * 16;
        uint32_t b = (uint32_t)(row * 128 + c16 * 16);
        bSw[j] = b ^ ((b >> 3) & 0x70);
    }
    const char* pAhi = (const char*)Ahi;
    const char* pAlo = (const char*)Alo;
    const char* pBhi = (const char*)Bhi;
    const char* pBlo = (const char*)Blo;

    auto load_chunk = [&](int chunk, int st) {
        uint32_t sb = sbase + st * STAGE_BYTES;
        size_t ko = (size_t)chunk * 128;               // 64 cols * 2B
#pragma unroll
        for (int j = 0; j < 8; j++) {
            cp16(sb + OFF_AHI + aSw[j], pAhi + aOff[j] + ko);
            cp16(sb + OFF_ALO + aSw[j], pAlo + aOff[j] + ko);
        }
#pragma unroll
        for (int j = 0; j < 4; j++) {
            cp16(sb + OFF_BHI + bSw[j], pBhi + bOff[j] + ko);
            cp16(sb + OFF_BLO + bSw[j], pBlo + bOff[j] + ko);
        }
        CP_COMMIT();
    };

    float acc[4][4][4];
#pragma unroll
    for (int i = 0; i < 4; i++)
#pragma unroll
        for (int j = 0; j < 4; j++)
#pragma unroll
            for (int c = 0; c < 4; c++) acc[i][j][c] = 0.f;

    load_chunk(0, 0);
    if (NC > 1) load_chunk(1, 1);

    // ldmatrix lane addressing
    const int aRow = lid & 15;
    const int aHi16 = ((lid >> 4) & 1) * 16;
    const int bRowSel = ((lid >> 4) & 1) * 8 + (lid & 7);
    const int bHi16 = ((lid >> 3) & 1) * 16;

    // double-buffered fragments
    uint32_t ah[2][4][4], al[2][4][4], bh[2][2][4], bl[2][2][4];

    for (int k = 0; k < NC; k++) {
        const int st = k & 1;
        if (k < NC - 1) asm volatile("cp.async.wait_group 1;" ::: "memory");
        else            asm volatile("cp.async.wait_group 0;" ::: "memory");
        __syncthreads();

        const uint32_t sb  = sbase + st * STAGE_BYTES;
        const uint32_t tAh = sb + OFF_AHI;
        const uint32_t tBh = sb + OFF_BHI;

        auto ld_frags = [&](int buf, int q) {
#pragma unroll
            for (int mi = 0; mi < 4; mi++) {
                uint32_t adr = sw_addr(tAh, wm + mi * 16 + aRow, q * 32 + aHi16);
                ldsm4(ah[buf][mi], adr);
                ldsm4(al[buf][mi], adr + (OFF_ALO - OFF_AHI));
            }
#pragma unroll
            for (int nj2 = 0; nj2 < 2; nj2++) {
                uint32_t adr = sw_addr(tBh, wn + nj2 * 16 + bRowSel, q * 32 + bHi16);
                ldsm4(bh[buf][nj2], adr);
                ldsm4(bl[buf][nj2], adr + (OFF_BLO - OFF_BHI));
            }
        };

        ld_frags(0, 0);
#pragma unroll
        for (int q = 0; q < 4; q++) {
            if (q < 3) ld_frags((q + 1) & 1, q + 1);   // prefetch next k16 fragments
            const int b = q & 1;
#pragma unroll
            for (int mi = 0; mi < 4; mi++)
#pragma unroll
                for (int nj = 0; nj < 4; nj++) {
                    uint32_t b0 = bh[b][nj >> 1][(nj & 1) * 2];
                    uint32_t b1 = bh[b][nj >> 1][(nj & 1) * 2 + 1];
                    uint32_t l0 = bl[b][nj >> 1][(nj & 1) * 2];
                    uint32_t l1 = bl[b][nj >> 1][(nj & 1) * 2 + 1];
                    mma16816(acc[mi][nj], ah[b][mi], b0, b1);
                    mma16816(acc[mi][nj], ah[b][mi], l0, l1);
                    mma16816(acc[mi][nj], al[b][mi], b0, b1);
                }
        }
        __syncthreads();                       // stage st free for the next load
        if (k + 2 < NC) load_chunk(k + 2, st);
    }

    // ---- epilogue ----
    const float* bp = bias + (size_t)e * Ndim + n0;
    const int rbase = wm + (lid >> 2);
    const int cquad = (lid & 3) * 2;

#pragma unroll
    for (int mi = 0; mi < 4; mi++) {
#pragma unroll
        for (int half = 0; half < 2; half++) {
            const int row = rbase + mi * 16 + half * 8;
            const int m = m0 + row;
            if (m >= cnt) continue;
            const int slot = off + m;
            int tok = 0; float wgt = 0.f;
            if (!IS_FC) { tok = g_slot_token[slot]; wgt = g_slot_w[slot]; }
#pragma unroll
            for (int nj = 0; nj < 4; nj++) {
                const int col = wn + nj * 8 + cquad;
                float v0 = acc[mi][nj][half * 2 + 0] + bp[col];
                float v1 = acc[mi][nj][half * 2 + 1] + bp[col + 1];
                if (IS_FC) {
                    float g0 = 0.5f * v0 * (1.f + erff(v0 * 0.70710678118654752f));
                    float g1 = 0.5f * v1 * (1.f + erff(v1 * 0.70710678118654752f));
                    __nv_bfloat16 h0 = __float2bfloat16(g0);
                    __nv_bfloat16 h1 = __float2bfloat16(g1);
                    __nv_bfloat16 q0 = __float2bfloat16(g0 - __bfloat162float(h0));
                    __nv_bfloat16 q1 = __float2bfloat16(g1 - __bfloat162float(h1));
                    size_t idx = (size_t)slot * Ndim + n0 + col;
                    *(uint32_t*)(g_hhi + idx) =
                        (uint32_t)__bfloat16_as_ushort(h0) |
                        ((uint32_t)__bfloat16_as_ushort(h1) << 16);
                    *(uint32_t*)(g_hlo + idx) =
                        (uint32_t)__bfloat16_as_ushort(q0) |
                        ((uint32_t)__bfloat16_as_ushort(q1) << 16);
                } else {
                    float* op = out + (size_t)tok * D_DIM + n0 + col;
                    atomicAdd(op + 0, v0 * wgt);
                    atomicAdd(op + 1, v1 * wgt);
                }
            }
        }
    }
}

// ------------------------------------------------------------------ launch
extern "C" void kernel_launch(void* const* d_in, const int* in_sizes, int n_in,
                              void* d_out, int out_size)
{
    const float* x      = (const float*)d_in[0];
    const float* rw     = (const float*)d_in[1];
    const float* w_fc   = (const float*)d_in[2];
    const float* b_fc   = (const float*)d_in[3];
    const float* w_proj = (const float*)d_in[4];
    const float* b_proj = (const float*)d_in[5];
    float* out = (float*)d_out;

    cudaFuncSetAttribute(k_mma_gemm<true>,  cudaFuncAttributeMaxDynamicSharedMemorySize, GEMM_SMEM);
    cudaFuncSetAttribute(k_mma_gemm<false>, cudaFuncAttributeMaxDynamicSharedMemorySize, GEMM_SMEM);

    cudaMemsetAsync(out, 0, (size_t)out_size * sizeof(float));
    void* pfill = nullptr;
    cudaGetSymbolAddress(&pfill, g_fill);
    cudaMemsetAsync(pfill, 0, E_EXP * sizeof(int));

    dim3 bw(32, 8);
    k_convw<<<dim3(F_DIM / 32, D_DIM / 32, E_EXP), bw>>>(w_fc,   D_DIM, F_DIM, 0);  // #1
    k_convw<<<dim3(D_DIM / 32, F_DIM / 32, E_EXP), bw>>>(w_proj, F_DIM, D_DIM, 1);  // #2

    k_router<<<T_TOKENS / 8, 256>>>(x, rw);                                          // #3

    k_mma_gemm<true ><<<dim3(EXP_CAP / 128, F_DIM / 64, E_EXP), 128, GEMM_SMEM>>>(b_fc, nullptr);  // #4 (profiled)
    k_mma_gemm<false><<<dim3(EXP_CAP / 128, D_DIM / 64, E_EXP), 128, GEMM_SMEM>>>(b_proj, out);    // #5
}